// round 16
// baseline (speedup 1.0000x reference)
#include <cuda_runtime.h>
#include <stdint.h>

#define FULL 0xffffffffu

constexpr int Bb = 8;
constexpr int Nn = 16384;
constexpr int Gg = 257;
constexpr int Kk = 32;
constexpr int NBX = 64;                // x-slabs
constexpr int NBY = 8;                 // y-bins per slab
constexpr int NC  = NBX * NBY;         // 512 cells
constexpr float LBM = 1e-3f;           // x-slab lb margin
constexpr float YM  = 1e-2f;           // y-window coordinate margin

// Sphere-grid centers, compile-time (exact lattice arithmetic; verified).
struct Centers { float x[Gg]; float y[Gg]; float z[Gg]; };
constexpr Centers make_centers() {
    Centers c{};
    int n = 0;
    for (int i = 0; i < 9; ++i)
        for (int j = 0; j < 9; ++j)
            for (int k = 0; k < 9; ++k) {
                const float x = -1.0f + 0.25f * (float)i;
                const float y = -1.0f + 0.25f * (float)j;
                const float z = -1.0f + 0.25f * (float)k;
                if (x * x + y * y + z * z <= 1.0f) {
                    c.x[n] = x; c.y[n] = y; c.z[n] = z; ++n;
                }
            }
    return c;
}
__constant__ Centers g_c = make_centers();

__device__ __forceinline__ int xbin(float x) {
    int s = (int)floorf((x + 2.0f) * 16.0f);   // 64 bins over [-2,2]
    return min(NBX - 1, max(0, s));
}
__device__ __forceinline__ int ybin(float y) {
    int s = (int)floorf((y + 2.0f) * 2.0f);    // 8 bins over [-2,2]
    return min(NBY - 1, max(0, s));
}

__device__ __forceinline__ unsigned long long ull_min(unsigned long long a,
                                                      unsigned long long b) {
    return a < b ? a : b;
}
__device__ __forceinline__ unsigned long long ull_max(unsigned long long a,
                                                      unsigned long long b) {
    return a < b ? b : a;
}

// smem layout (float units). sidx FIRST so the smerge overlay is 8B-aligned.
// Coord arrays padded +47 (max masked overread index is Nn+31).
constexpr int CPAD = 47;
constexpr int SID = 0;                             // (Nn+64) u16 = 8224 floats
constexpr int SXO = (Nn + 64) / 2;                 // 8224
constexpr int SYO = SXO + (Nn + CPAD);
constexpr int SZO = SYO + (Nn + CPAD);
constexpr int VTH = SZO + (Nn + CPAD);
constexpr int SPR = VTH + 32;
constexpr int SMEM_FLOATS = SPR + (NC + 1);        // 232,184 B

__global__ __launch_bounds__(1024, 1)
void knn_group_kernel(const float* __restrict__ xyz,
                      const float* __restrict__ labels,
                      const float* __restrict__ inside,
                      float* __restrict__ out) {
    extern __shared__ float s[];
    unsigned short* sidx = reinterpret_cast<unsigned short*>(s + SID);
    unsigned long long* smerge =
        reinterpret_cast<unsigned long long*>(s + SID);   // overlay after search
    float* sxs = s + SXO;      // cell-sorted coords
    float* sys = s + SYO;
    float* szs = s + SZO;
    volatile float* vth = reinterpret_cast<volatile float*>(s + VTH);
    int* sPre = reinterpret_cast<int*>(s + SPR);   // sPre[c]=start of cell c

    const int b = blockIdx.y;
    const int tid = threadIdx.x;
    const int wid  = tid >> 5;
    const int lane = tid & 31;
    const float* src = xyz + (size_t)b * Nn * 3;

    // Phase 0: zero counters + thresholds.
    if (tid < NC) sPre[1 + tid] = 0;
    if (tid < 32) vth[tid] = __int_as_float(0x7f800000);   // +inf
    __syncthreads();

    // Phase 1: histogram straight from global AoS (L2-resident); cache cells.
    int cell16[16];
    #pragma unroll
    for (int k = 0; k < 16; ++k) {
        const int p = tid + 1024 * k;
        const int c = xbin(src[3 * p]) * NBY + ybin(src[3 * p + 1]);
        cell16[k] = c;
        atomicAdd(&sPre[1 + c], 1);
    }
    __syncthreads();

    // Phase 2: warp-0 shfl-scan of 512 counts -> sPre[1+c] = cell start.
    if (wid == 0) {
        const int base = lane * 16;
        int loc[16];
        int run = 0;
        #pragma unroll
        for (int k = 0; k < 16; ++k) { loc[k] = run; run += sPre[1 + base + k]; }
        int v = run;
        #pragma unroll
        for (int o = 1; o < 32; o <<= 1) {
            const int u = __shfl_up_sync(FULL, v, o);
            if (lane >= o) v += u;
        }
        const int excl = v - run;
        #pragma unroll
        for (int k = 0; k < 16; ++k) sPre[1 + base + k] = excl + loc[k];
        if (lane == 0) sPre[0] = 0;
    }
    __syncthreads();

    // Phase 3: scatter values + orig idx into SORTED smem SoA. Cursors
    // sPre[1+c] become cell ends: cell c spans [sPre[c], sPre[c+1]).
    // Intra-cell order nondeterministic; output invariant (keys carry idx).
    #pragma unroll
    for (int k = 0; k < 16; ++k) {
        const int p = tid + 1024 * k;
        const float x = src[3 * p + 0];
        const float y = src[3 * p + 1];
        const float z = src[3 * p + 2];
        const int pos = atomicAdd(&sPre[1 + cell16[k]], 1);
        sxs[pos] = x; sys[pos] = y; szs[pos] = z;
        sidx[pos] = (unsigned short)p;
    }
    __syncthreads();

    const int gi      = wid >> 1;
    const int slabpar = wid & 1;       // each warp owns one slab parity
    const int g       = blockIdx.x * 16 + gi;
    const bool active = (g < Gg);

    unsigned long long key = ~0ull;
    float cx = 0.f, cy = 0.f, cz = 0.f;

    if (active) {
        cx = g_c.x[g]; cy = g_c.y[g]; cz = g_c.z[g];
        const float c2 = cx * cx + cy * cy + cz * cz;

        // FROZEN precision model (verified rel_err == 0).
        auto d2exact = [&](float x, float y, float z) -> float {
            const float x2 = __fmaf_rn(z, z, __fmaf_rn(y, y, __fmul_rn(x, x)));
            const float dt = __fmaf_rn(cz, z, __fmaf_rn(cy, y, __fmul_rn(cx, x)));
            return __fsub_rn(__fadd_rn(c2, x2), __fmul_rn(2.0f, dt));
        };
        // key = d2bits(32) | origidx(16) | pos(16): reference order
        // (d2 asc, orig idx asc); unique pos tail never decides. (proven)
        auto mkkey = [&](float d2v, int pos) -> unsigned long long {
            unsigned uu = __float_as_uint(d2v);
            uu = (uu & 0x80000000u) ? ~uu : (uu | 0x80000000u);
            const unsigned oi = (unsigned)sidx[pos];
            return ((unsigned long long)uu << 32) | (oi << 16) | (unsigned)pos;
        };

        const int pw = wid ^ 1;

        unsigned long long thresh = ~0ull;
        float thresh_f = __int_as_float(0x7f800000);

        auto insert_nk = [&](unsigned long long nk) {
            unsigned m = __ballot_sync(FULL, nk < thresh);
            while (m) {
                const int srcl = __ffs(m) - 1;
                m &= m - 1;
                const unsigned long long cand = __shfl_sync(FULL, nk, srcl);
                const int pos = __popc(__ballot_sync(FULL, key < cand));
                const unsigned long long up = __shfl_up_sync(FULL, key, 1);
                if (lane > pos)       key = up;
                else if (lane == pos) key = cand;
            }
        };
        auto round_refresh = [&]() {
            thresh = __shfl_sync(FULL, key, 31);
            const unsigned tu = (unsigned)(thresh >> 32);
            const unsigned ob = (tu & 0x80000000u) ? (tu ^ 0x80000000u) : ~tu;
            thresh_f = __uint_as_float(ob);
            if (lane == 0)   // publish (NaN -> +inf so partner stays live)
                vth[wid] = (thresh_f == thresh_f) ? thresh_f
                                                  : __int_as_float(0x7f800000);
        };

        // Outward sweep over my-parity slabs, nearest-first.
        auto lbof = [&](int sl) -> float {
            if (sl < 0 || sl > NBX - 1) return __int_as_float(0x7f800000);
            const float el = -2.0f + 0.0625f * (float)sl;
            const float eh = el + 0.0625f;
            const float dx = (cx < el) ? (el - cx)
                                       : ((cx > eh) ? (cx - eh) : 0.0f);
            return dx * dx;
        };
        const int s0 = xbin(cx);
        int l = s0 - (((s0 & 1) != slabpar) ? 1 : 0);
        int r = l + 2;
        float lbl = lbof(l), lbr = lbof(r);
        bool first = true;

        for (int iter = 0; iter < 32; ++iter) {
            const float lbmin = fminf(lbl, lbr);
            const float tg0 = fminf(thresh_f, vth[pw]);   // NaN-safe
            if (lbmin - LBM > tg0) break;
            int sl;
            if (lbl <= lbr) { sl = l; l -= 2; lbl = lbof(l); }
            else            { sl = r; r += 2; lbr = lbof(r); }

            // y-window from current (monotone -> conservative) threshold.
            const float rw = sqrtf(tg0) + YM;             // inf-safe
            const int yb0 = min(NBY - 1, max(0, (int)floorf((cy - rw + 2.0f) * 2.0f)));
            const int yb1 = min(NBY - 1, max(0, (int)floorf((cy + rw + 2.0f) * 2.0f)));
            int st = sPre[sl * NBY + yb0];
            const int en = sPre[sl * NBY + yb1 + 1];

            // Partner threshold hoisted per slab (stale = looser = exact).
            const float pthr = vth[pw];

            if (first) {   // prefill: bitonic sort-32 of first <=32 points
                const int p = st + lane;                  // <= Nn+31, padded
                key = (p < en)
                    ? mkkey(d2exact(sxs[p], sys[p], szs[p]), p) : ~0ull;
                #pragma unroll
                for (int k = 2; k <= 32; k <<= 1) {
                    #pragma unroll
                    for (int j = k >> 1; j >= 1; j >>= 1) {
                        const unsigned long long o = __shfl_xor_sync(FULL, key, j);
                        const bool dir = ((lane & k) == 0);
                        const bool keep_min = (((lane & j) == 0) == dir);
                        key = keep_min ? ull_min(key, o) : ull_max(key, o);
                    }
                }
                round_refresh();
                st = min(st + 32, en);
                first = false;
            }

            for (int p0 = st; p0 < en; p0 += 64) {
                const int posA = p0 + lane;
                const int posB = posA + 32;               // <= Nn+31, padded
                const bool vA = (posA < en), vB = (posB < en);
                const float dA = d2exact(sxs[posA], sys[posA], szs[posA]);
                const float dB = d2exact(sxs[posB], sys[posB], szs[posB]);
                const float tg = fminf(thresh_f, pthr);
                const bool hA = vA && (dA <= tg);
                const bool hB = vB && (dB <= tg);
                if (__ballot_sync(FULL, hA || hB)) {
                    insert_nk(hA ? mkkey(dA, posA) : ~0ull);
                    insert_nk(hB ? mkkey(dB, posB) : ~0ull);
                    round_refresh();
                }
            }
        }
    }

    __syncthreads();                     // sidx reads done; overlay smerge
    if (active) smerge[wid * 32 + lane] = key;
    __syncthreads();

    if (active && (slabpar == 0)) {
        // min(A[r], B[31-r]) = lowest-32 of union (bitonic), then sort.
        unsigned long long mk = ull_min(key, smerge[(wid + 1) * 32 + (31 - lane)]);
        #pragma unroll
        for (int d = 16; d >= 1; d >>= 1) {
            const unsigned long long o = __shfl_xor_sync(FULL, mk, d);
            mk = (lane & d) ? ull_max(mk, o) : ull_min(mk, o);
        }

        const int pos = (int)(mk & 0xffffu);          // sorted position
        const int idx = (int)((mk >> 16) & 0xffffu);  // original index
        const float px = sxs[pos];
        const float py = sys[pos];
        const float pz = szs[pos];
        const int bg = b * Gg + g;

        float* o0 = out;                                // neigh [B,G,32,3]
        float* o1 = o0 + (size_t)Bb * Gg * Kk * 3;      // center [B,G,3]
        float* o2 = o1 + (size_t)Bb * Gg * 3;           // labels [B,G,32,1]
        float* o3 = o2 + (size_t)Bb * Gg * Kk;          // idx    [B,G,32]
        float* o4 = o3 + (size_t)Bb * Gg * Kk;          // inside [B,G,32,1]

        const int r0 = (bg * Kk + lane) * 3;
        o0[r0 + 0] = __fsub_rn(px, cx);
        o0[r0 + 1] = __fsub_rn(py, cy);
        o0[r0 + 2] = __fsub_rn(pz, cz);
        if (lane == 0) {
            o1[bg * 3 + 0] = cx;
            o1[bg * 3 + 1] = cy;
            o1[bg * 3 + 2] = cz;
        }
        o2[bg * Kk + lane] = labels[b * Nn + idx];
        o3[bg * Kk + lane] = (float)idx;
        o4[bg * Kk + lane] = inside[b * Nn + idx];
    }
}

extern "C" void kernel_launch(void* const* d_in, const int* in_sizes, int n_in,
                              void* d_out, int out_size) {
    const float* xyz    = (const float*)d_in[0];
    const float* labels = (const float*)d_in[1];
    const float* inside = (const float*)d_in[2];
    float* out = (float*)d_out;

    (void)in_sizes; (void)n_in; (void)out_size;

    const int smem = SMEM_FLOATS * sizeof(float);   // 232,184 B < 232,448
    cudaFuncSetAttribute(knn_group_kernel,
                         cudaFuncAttributeMaxDynamicSharedMemorySize, smem);
    dim3 grid((Gg + 15) / 16, Bb);
    knn_group_kernel<<<grid, 1024, smem>>>(xyz, labels, inside, out);
}

// round 17
// speedup vs baseline: 1.0432x; 1.0432x over previous
#include <cuda_runtime.h>
#include <stdint.h>

#define FULL 0xffffffffu

constexpr int Bb = 8;
constexpr int Nn = 16384;
constexpr int Gg = 257;
constexpr int Kk = 32;
constexpr int NBX = 64;                // x-slabs
constexpr int NBY = 8;                 // y-bins per slab
constexpr int NC  = NBX * NBY;         // 512 cells
constexpr float LBM = 1e-3f;           // x-slab lb margin
constexpr float YM  = 1e-2f;           // y-window coordinate margin

// Sphere-grid centers, compile-time (exact lattice arithmetic; verified).
struct Centers { float x[Gg]; float y[Gg]; float z[Gg]; };
constexpr Centers make_centers() {
    Centers c{};
    int n = 0;
    for (int i = 0; i < 9; ++i)
        for (int j = 0; j < 9; ++j)
            for (int k = 0; k < 9; ++k) {
                const float x = -1.0f + 0.25f * (float)i;
                const float y = -1.0f + 0.25f * (float)j;
                const float z = -1.0f + 0.25f * (float)k;
                if (x * x + y * y + z * z <= 1.0f) {
                    c.x[n] = x; c.y[n] = y; c.z[n] = z; ++n;
                }
            }
    return c;
}
__constant__ Centers g_c = make_centers();

__device__ __forceinline__ int xbin(float x) {
    int s = (int)floorf((x + 2.0f) * 16.0f);   // 64 bins over [-2,2]
    return min(NBX - 1, max(0, s));
}
__device__ __forceinline__ int ybin(float y) {
    int s = (int)floorf((y + 2.0f) * 2.0f);    // 8 bins over [-2,2]
    return min(NBY - 1, max(0, s));
}

__device__ __forceinline__ unsigned long long ull_min(unsigned long long a,
                                                      unsigned long long b) {
    return a < b ? a : b;
}
__device__ __forceinline__ unsigned long long ull_max(unsigned long long a,
                                                      unsigned long long b) {
    return a < b ? b : a;
}

// smem layout (float units): AoS cloud (original order), then perm (+64 pad
// for masked overreads: max index en+62 <= Nn+63), vth, sPre.
constexpr int AOS = 0;                             // 3*Nn floats
constexpr int PRM = 3 * Nn;                        // (Nn+64) u16
constexpr int VTH = PRM + (Nn + 64) / 2;           // 32 floats
constexpr int SPR = VTH + 32;                      // NC+1 ints
constexpr int SMEM_FLOATS = SPR + (NC + 1);        // 231,684 B

__global__ __launch_bounds__(1024, 1)
void knn_group_kernel(const float* __restrict__ xyz,
                      const float* __restrict__ labels,
                      const float* __restrict__ inside,
                      float* __restrict__ out) {
    extern __shared__ float s[];
    unsigned short* perm = reinterpret_cast<unsigned short*>(s + PRM);
    unsigned long long* smerge =
        reinterpret_cast<unsigned long long*>(s + PRM);   // overlay post-search
    volatile float* vth = reinterpret_cast<volatile float*>(s + VTH);
    int* sPre = reinterpret_cast<int*>(s + SPR);   // sPre[c]=start of cell c

    const int b = blockIdx.y;
    const int tid = threadIdx.x;
    const int wid  = tid >> 5;
    const int lane = tid & 31;

    // Phase 0: zero counters + thresholds; stage AoS cloud (pure copy).
    if (tid < NC) sPre[1 + tid] = 0;
    if (tid < 32) vth[tid] = __int_as_float(0x7f800000);   // +inf
    {
        const float4* src4 = reinterpret_cast<const float4*>(xyz + (size_t)b * Nn * 3);
        float4* dst4 = reinterpret_cast<float4*>(s);
        #pragma unroll
        for (int k = 0; k < 12; ++k) {            // 12288 float4 total
            const int i = tid + 1024 * k;
            dst4[i] = src4[i];
        }
    }
    __syncthreads();

    // Phase 1: histogram from smem AoS (stride-3 LDS = conflict-free).
    #pragma unroll
    for (int k = 0; k < 16; ++k) {
        const int p = tid + 1024 * k;
        atomicAdd(&sPre[1 + xbin(s[3 * p]) * NBY + ybin(s[3 * p + 1])], 1);
    }
    __syncthreads();

    // Phase 2: warp-0 shfl-scan of 512 counts -> sPre[1+c] = cell start.
    if (wid == 0) {
        const int base = lane * 16;
        int loc[16];
        int run = 0;
        #pragma unroll
        for (int k = 0; k < 16; ++k) { loc[k] = run; run += sPre[1 + base + k]; }
        int v = run;
        #pragma unroll
        for (int o = 1; o < 32; o <<= 1) {
            const int u = __shfl_up_sync(FULL, v, o);
            if (lane >= o) v += u;
        }
        const int excl = v - run;
        #pragma unroll
        for (int k = 0; k < 16; ++k) sPre[1 + base + k] = excl + loc[k];
        if (lane == 0) sPre[0] = 0;
    }
    __syncthreads();

    // Phase 3: scatter 16-bit permutation; cursors sPre[1+c] become cell
    // ends: cell c spans [sPre[c], sPre[c+1]). Intra-cell order is
    // nondeterministic; output invariant (keys carry orig idx; proven).
    #pragma unroll
    for (int k = 0; k < 16; ++k) {
        const int p = tid + 1024 * k;
        const int cell = xbin(s[3 * p]) * NBY + ybin(s[3 * p + 1]);
        const int pos = atomicAdd(&sPre[1 + cell], 1);
        perm[pos] = (unsigned short)p;
    }
    if (tid < 64) perm[Nn + tid] = 0;   // pad: overreads gather point 0
    __syncthreads();

    const int gi      = wid >> 1;
    const int slabpar = wid & 1;       // each warp owns one slab parity
    const int g       = blockIdx.x * 16 + gi;
    const bool active = (g < Gg);

    unsigned long long key = ~0ull;
    float cx = 0.f, cy = 0.f, cz = 0.f;

    if (active) {
        cx = g_c.x[g]; cy = g_c.y[g]; cz = g_c.z[g];
        const float c2 = cx * cx + cy * cy + cz * cz;

        // FROZEN precision model (verified rel_err == 0).
        auto d2exact = [&](float x, float y, float z) -> float {
            const float x2 = __fmaf_rn(z, z, __fmaf_rn(y, y, __fmul_rn(x, x)));
            const float dt = __fmaf_rn(cz, z, __fmaf_rn(cy, y, __fmul_rn(cx, x)));
            return __fsub_rn(__fadd_rn(c2, x2), __fmul_rn(2.0f, dt));
        };
        // key = d2bits(32) | origidx(32): exact reference order (d2, idx).
        auto mkkey = [](float d2v, int p) -> unsigned long long {
            unsigned uu = __float_as_uint(d2v);
            uu = (uu & 0x80000000u) ? ~uu : (uu | 0x80000000u);
            return ((unsigned long long)uu << 32) | (unsigned)p;
        };

        const int pw = wid ^ 1;

        unsigned long long thresh = ~0ull;
        float thresh_f = __int_as_float(0x7f800000);

        auto insert_nk = [&](unsigned long long nk) {
            unsigned m = __ballot_sync(FULL, nk < thresh);
            while (m) {
                const int srcl = __ffs(m) - 1;
                m &= m - 1;
                const unsigned long long cand = __shfl_sync(FULL, nk, srcl);
                const int pos = __popc(__ballot_sync(FULL, key < cand));
                const unsigned long long up = __shfl_up_sync(FULL, key, 1);
                if (lane > pos)       key = up;
                else if (lane == pos) key = cand;
            }
        };
        auto round_refresh = [&]() {
            thresh = __shfl_sync(FULL, key, 31);
            const unsigned tu = (unsigned)(thresh >> 32);
            const unsigned ob = (tu & 0x80000000u) ? (tu ^ 0x80000000u) : ~tu;
            thresh_f = __uint_as_float(ob);
            if (lane == 0)   // publish (NaN -> +inf so partner stays live)
                vth[wid] = (thresh_f == thresh_f) ? thresh_f
                                                  : __int_as_float(0x7f800000);
        };

        // Outward sweep over my-parity slabs, nearest-first.
        auto lbof = [&](int sl) -> float {
            if (sl < 0 || sl > NBX - 1) return __int_as_float(0x7f800000);
            const float el = -2.0f + 0.0625f * (float)sl;
            const float eh = el + 0.0625f;
            const float dx = (cx < el) ? (el - cx)
                                       : ((cx > eh) ? (cx - eh) : 0.0f);
            return dx * dx;
        };
        const int s0 = xbin(cx);
        int l = s0 - (((s0 & 1) != slabpar) ? 1 : 0);
        int r = l + 2;
        float lbl = lbof(l), lbr = lbof(r);
        bool first = true;

        for (int iter = 0; iter < 32; ++iter) {
            const float lbmin = fminf(lbl, lbr);
            const float tg0 = fminf(thresh_f, vth[pw]);   // NaN-safe
            if (lbmin - LBM > tg0) break;
            int sl;
            if (lbl <= lbr) { sl = l; l -= 2; lbl = lbof(l); }
            else            { sl = r; r += 2; lbr = lbof(r); }

            // y-window from current (monotone -> conservative) threshold.
            const float rw = sqrtf(tg0) + YM;             // inf-safe
            const int yb0 = min(NBY - 1, max(0, (int)floorf((cy - rw + 2.0f) * 2.0f)));
            const int yb1 = min(NBY - 1, max(0, (int)floorf((cy + rw + 2.0f) * 2.0f)));
            int st = sPre[sl * NBY + yb0];
            const int en = sPre[sl * NBY + yb1 + 1];

            // Partner threshold hoisted per slab (stale = looser = exact).
            const float pthr = vth[pw];

            if (first) {   // prefill: bitonic sort-32 of first <=32 points
                const int pp = (int)perm[st + lane];      // padded
                key = (st + lane < en)
                    ? mkkey(d2exact(s[3 * pp], s[3 * pp + 1], s[3 * pp + 2]), pp)
                    : ~0ull;
                #pragma unroll
                for (int k = 2; k <= 32; k <<= 1) {
                    #pragma unroll
                    for (int j = k >> 1; j >= 1; j >>= 1) {
                        const unsigned long long o = __shfl_xor_sync(FULL, key, j);
                        const bool dir = ((lane & k) == 0);
                        const bool keep_min = (((lane & j) == 0) == dir);
                        key = keep_min ? ull_min(key, o) : ull_max(key, o);
                    }
                }
                round_refresh();
                st = min(st + 32, en);
                first = false;
            }

            for (int p0 = st; p0 < en; p0 += 64) {
                const int posA = p0 + lane;
                const int posB = posA + 32;               // <= en+62, padded
                const bool vA = (posA < en), vB = (posB < en);
                const int pA = (int)perm[posA];
                const int pB = (int)perm[posB];
                const float dA = d2exact(s[3 * pA], s[3 * pA + 1], s[3 * pA + 2]);
                const float dB = d2exact(s[3 * pB], s[3 * pB + 1], s[3 * pB + 2]);
                const float tg = fminf(thresh_f, pthr);
                const bool hA = vA && (dA <= tg);
                const bool hB = vB && (dB <= tg);
                if (__ballot_sync(FULL, hA || hB)) {
                    insert_nk(hA ? mkkey(dA, pA) : ~0ull);
                    insert_nk(hB ? mkkey(dB, pB) : ~0ull);
                    round_refresh();
                }
            }
        }
    }

    __syncthreads();                     // perm reads done; overlay smerge
    if (active) smerge[wid * 32 + lane] = key;
    __syncthreads();

    if (active && (slabpar == 0)) {
        // min(A[r], B[31-r]) = lowest-32 of union (bitonic), then sort.
        unsigned long long mk = ull_min(key, smerge[(wid + 1) * 32 + (31 - lane)]);
        #pragma unroll
        for (int d = 16; d >= 1; d >>= 1) {
            const unsigned long long o = __shfl_xor_sync(FULL, mk, d);
            mk = (lane & d) ? ull_max(mk, o) : ull_min(mk, o);
        }

        const int idx = (int)(mk & 0xffffffffu);   // original index
        const float px = s[3 * idx + 0];
        const float py = s[3 * idx + 1];
        const float pz = s[3 * idx + 2];
        const int bg = b * Gg + g;

        float* o0 = out;                                // neigh [B,G,32,3]
        float* o1 = o0 + (size_t)Bb * Gg * Kk * 3;      // center [B,G,3]
        float* o2 = o1 + (size_t)Bb * Gg * 3;           // labels [B,G,32,1]
        float* o3 = o2 + (size_t)Bb * Gg * Kk;          // idx    [B,G,32]
        float* o4 = o3 + (size_t)Bb * Gg * Kk;          // inside [B,G,32,1]

        const int r0 = (bg * Kk + lane) * 3;
        o0[r0 + 0] = __fsub_rn(px, cx);
        o0[r0 + 1] = __fsub_rn(py, cy);
        o0[r0 + 2] = __fsub_rn(pz, cz);
        if (lane == 0) {
            o1[bg * 3 + 0] = cx;
            o1[bg * 3 + 1] = cy;
            o1[bg * 3 + 2] = cz;
        }
        o2[bg * Kk + lane] = labels[b * Nn + idx];
        o3[bg * Kk + lane] = (float)idx;
        o4[bg * Kk + lane] = inside[b * Nn + idx];
    }
}

extern "C" void kernel_launch(void* const* d_in, const int* in_sizes, int n_in,
                              void* d_out, int out_size) {
    const float* xyz    = (const float*)d_in[0];
    const float* labels = (const float*)d_in[1];
    const float* inside = (const float*)d_in[2];
    float* out = (float*)d_out;

    (void)in_sizes; (void)n_in; (void)out_size;

    const int smem = SMEM_FLOATS * sizeof(float);   // 231,684 B < 232,448
    cudaFuncSetAttribute(knn_group_kernel,
                         cudaFuncAttributeMaxDynamicSharedMemorySize, smem);
    dim3 grid((Gg + 15) / 16, Bb);
    knn_group_kernel<<<grid, 1024, smem>>>(xyz, labels, inside, out);
}